// round 9
// baseline (speedup 1.0000x reference)
#include <cuda_runtime.h>
#include <cuda_bf16.h>
#include <cstdint>
#include <math.h>

#define BATCH 8
#define CDIM 192
#define C3 576
#define HEADS 8
#define CH 24
#define HW 16384
#define KTOT 576          // logical split-K: [Wh|Wh|Wl] x [xh|xl|xh(wrapped)]
#define KB_PHYS 384       // physical B width (hi|lo); k>=384 wraps to hi
#define RBQK 16           // rowblocks (8 rows each) in fused qk kernel

// ---------------- scratch ----------------
__device__ float g_qkv[BATCH * C3 * HW];                        // fp32 qkv (301 MB)
__device__ __nv_bfloat16 g_B1[(size_t)BATCH * HW * KB_PHYS];    // x split/transposed (100 MB)
__device__ __nv_bfloat16 g_V[(size_t)BATCH * HW * KB_PHYS];     // v dw split/transposed (100 MB)
__device__ __nv_bfloat16 g_A1[640 * KTOT];                      // w_qkv split (rows 576..639 = 0)
__device__ __nv_bfloat16 g_A2[BATCH * 256 * KTOT];              // W2 split (rows 192..255 = 0)
__device__ float g_var[BATCH * CDIM];
__device__ float g_attn_part[BATCH * HEADS * RBQK * CH * CH];
__device__ float g_nrm_part[BATCH * HEADS * RBQK * 48];
__device__ float g_attn[BATCH * HEADS * CH * CH];

// ---------------- helpers ----------------
__device__ __forceinline__ uint32_t smem_u32(const void* p) {
    uint32_t a;
    asm("{ .reg .u64 t; cvta.to.shared.u64 t, %1; cvt.u32.u64 %0, t; }" : "=r"(a) : "l"(p));
    return a;
}
#define CP_ASYNC16(s, g) \
    asm volatile("cp.async.cg.shared.global [%0], [%1], 16;" :: "r"(s), "l"(g) : "memory")
#define CP_COMMIT asm volatile("cp.async.commit_group;" ::: "memory")
#define CP_WAIT0 asm volatile("cp.async.wait_group 0;" ::: "memory")

__device__ __forceinline__ void ldm_x4(uint32_t* d, uint32_t addr) {
    asm volatile("ldmatrix.sync.aligned.m8n8.x4.shared.b16 {%0,%1,%2,%3}, [%4];"
                 : "=r"(d[0]), "=r"(d[1]), "=r"(d[2]), "=r"(d[3]) : "r"(addr));
}
__device__ __forceinline__ void mma16816(float* c, const uint32_t* a, uint32_t b0, uint32_t b1) {
    asm volatile(
        "mma.sync.aligned.m16n8k16.row.col.f32.bf16.bf16.f32 "
        "{%0,%1,%2,%3}, {%4,%5,%6,%7}, {%8,%9}, {%0,%1,%2,%3};"
        : "+f"(c[0]), "+f"(c[1]), "+f"(c[2]), "+f"(c[3])
        : "r"(a[0]), "r"(a[1]), "r"(a[2]), "r"(a[3]), "r"(b0), "r"(b1));
}
__device__ __forceinline__ uint32_t bfsplit_pack(float v) {
    __nv_bfloat16 hi = __float2bfloat16(v);
    __nv_bfloat16 lo = __float2bfloat16(v - __bfloat162float(hi));
    return (uint32_t)__bfloat16_as_ushort(hi) | ((uint32_t)__bfloat16_as_ushort(lo) << 16);
}

// ---------------- K1: depthwise 3x3 on x + unbiased variance ----------------
__global__ void k_var(const float* __restrict__ x, const float* __restrict__ w_dw) {
    int bc = blockIdx.x;
    const float* in = x + (size_t)bc * HW;
    const float* wp = w_dw + (bc % CDIM) * 9;
    float wv[9];
#pragma unroll
    for (int i = 0; i < 9; i++) wv[i] = wp[i];
    float s1 = 0.f, s2 = 0.f;
    for (int idx = threadIdx.x; idx < HW; idx += blockDim.x) {
        int y = idx >> 7, xx = idx & 127;
        float a = 0.f;
#pragma unroll
        for (int dy = 0; dy < 3; dy++) {
            int yy = y + dy - 1;
            if (yy < 0 || yy > 127) continue;
            const float* row = in + yy * 128;
#pragma unroll
            for (int dx = 0; dx < 3; dx++) {
                int xc = xx + dx - 1;
                if (xc < 0 || xc > 127) continue;
                a += wv[dy * 3 + dx] * row[xc];
            }
        }
        s1 += a; s2 += a * a;
    }
#pragma unroll
    for (int o = 16; o; o >>= 1) {
        s1 += __shfl_xor_sync(0xffffffffu, s1, o);
        s2 += __shfl_xor_sync(0xffffffffu, s2, o);
    }
    __shared__ float r1[8], r2[8];
    if ((threadIdx.x & 31) == 0) { r1[threadIdx.x >> 5] = s1; r2[threadIdx.x >> 5] = s2; }
    __syncthreads();
    if (threadIdx.x == 0) {
        float t1 = 0.f, t2 = 0.f;
#pragma unroll
        for (int i = 0; i < 8; i++) { t1 += r1[i]; t2 += r2[i]; }
        g_var[bc] = (t2 - t1 * t1 * (1.0f / 16384.0f)) * (1.0f / 16383.0f);
    }
}

// ---------------- K2: split+transpose x -> g_B1[b][n][384] = [xh | xl] ----------------
__global__ void k_splitB(const float* __restrict__ x) {
    extern __shared__ unsigned int sh[];   // [256][65]
    int nt = blockIdx.x, cg = blockIdx.y, b = blockIdx.z;
    int t = threadIdx.x;
    int n0 = nt * 256;
    const float* xb = x + ((size_t)b * CDIM + cg * 64) * HW + n0;
#pragma unroll 4
    for (int j = 0; j < 64; j++)
        sh[t * 65 + j] = bfsplit_pack(xb[(size_t)j * HW + t]);
    __syncthreads();
    __nv_bfloat16* Bb = g_B1 + (size_t)b * HW * KB_PHYS;
    int lane = t & 31, w = t >> 5;
    for (int r = w; r < 256; r += 8) {
        unsigned int e0 = sh[r * 65 + lane * 2];
        unsigned int e1 = sh[r * 65 + lane * 2 + 1];
        unsigned int hi2 = (e0 & 0xFFFFu) | (e1 << 16);
        unsigned int lo2 = (e0 >> 16) | (e1 & 0xFFFF0000u);
        size_t rowb = (size_t)(n0 + r) * KB_PHYS + cg * 64 + lane * 2;
        *(unsigned int*)(Bb + rowb) = hi2;
        *(unsigned int*)(Bb + rowb + 192) = lo2;
    }
}

// ---------------- K3: split w_qkv -> g_A1[m][576] = [Wh | Wh | Wl] ----------------
__global__ void k_prepA1(const float* __restrict__ w_qkv) {
    int m = blockIdx.x, c = threadIdx.x;
    unsigned int pk = bfsplit_pack(w_qkv[m * CDIM + c]);
    __nv_bfloat16 hi = __ushort_as_bfloat16((unsigned short)(pk & 0xFFFF));
    __nv_bfloat16 lo = __ushort_as_bfloat16((unsigned short)(pk >> 16));
    g_A1[m * KTOT + c] = hi;
    g_A1[m * KTOT + 192 + c] = hi;
    g_A1[m * KTOT + 384 + c] = lo;
}

// ---------------- K4: bf16 HMMA GEMM, BM=128 BN=64 BK=64, 2-stage, 4 CTA/SM ----------------
#define BM 128
#define BN 64
#define BK 64
#define KITERS (KTOT / BK)     // 9
#define SROW 72                // 64 + 8 pad halves
#define STAGES 2

__global__ __launch_bounds__(256, 4)
void k_gemm_mma(const __nv_bfloat16* __restrict__ A, const __nv_bfloat16* __restrict__ B,
                float* __restrict__ C, int M_valid,
                long long sA, long long sB, long long sC) {
    extern __shared__ __nv_bfloat16 smbuf[];
    __nv_bfloat16* Asm = smbuf;                          // STAGES * BM * SROW
    __nv_bfloat16* Bsm = smbuf + STAGES * BM * SROW;     // STAGES * BN * SROW
    int tid = threadIdx.x, lane = tid & 31, wid = tid >> 5;
    int wm = wid & 3, wn = wid >> 2;          // 4 warps M x 2 warps N, warp tile 32x32
    int n0 = blockIdx.x * BN, m0 = blockIdx.y * BM, bz = blockIdx.z;
    const __nv_bfloat16* Ab = A + (size_t)bz * sA;
    const __nv_bfloat16* Bb = B + (size_t)bz * sB;
    float* Cb = C + (size_t)bz * sC;

    float acc[2][4][4];
#pragma unroll
    for (int im = 0; im < 2; im++)
#pragma unroll
        for (int in = 0; in < 4; in++)
#pragma unroll
            for (int q = 0; q < 4; q++) acc[im][in][q] = 0.f;

#define LOAD_STAGE(s, kk)                                                            \
    do {                                                                             \
        __nv_bfloat16* As_ = Asm + (s) * BM * SROW;                                  \
        __nv_bfloat16* Bs_ = Bsm + (s) * BN * SROW;                                  \
        int kb_ = ((kk) >= KB_PHYS) ? (kk) - KB_PHYS : (kk);                         \
        _Pragma("unroll")                                                            \
        for (int p = 0; p < 4; p++) {                                                \
            int i_ = tid + p * 256;                                                  \
            int r_ = i_ >> 3, cc_ = i_ & 7;                                          \
            CP_ASYNC16(smem_u32(As_ + r_ * SROW + cc_ * 8),                          \
                       Ab + (size_t)(m0 + r_) * KTOT + (kk) + cc_ * 8);              \
        }                                                                            \
        _Pragma("unroll")                                                            \
        for (int p = 0; p < 2; p++) {                                                \
            int i_ = tid + p * 256;                                                  \
            int r_ = i_ >> 3, cc_ = i_ & 7;                                          \
            CP_ASYNC16(smem_u32(Bs_ + r_ * SROW + cc_ * 8),                          \
                       Bb + (size_t)(n0 + r_) * KB_PHYS + kb_ + cc_ * 8);            \
        }                                                                            \
    } while (0)

    LOAD_STAGE(0, 0); CP_COMMIT;

    for (int it = 0; it < KITERS; it++) {
        CP_WAIT0;
        __syncthreads();
        if (it + 1 < KITERS) {
            LOAD_STAGE((it + 1) & 1, (it + 1) * BK);
        }
        CP_COMMIT;
        const __nv_bfloat16* As = Asm + (it & 1) * BM * SROW;
        const __nv_bfloat16* Bs = Bsm + (it & 1) * BN * SROW;
#pragma unroll
        for (int ks = 0; ks < 4; ks++) {
            int k0 = ks * 16;
            uint32_t af[2][4], bfr[2][4];
#pragma unroll
            for (int im = 0; im < 2; im++)
                ldm_x4(af[im], smem_u32(As + (wm * 32 + im * 16 + (lane & 15)) * SROW +
                                        k0 + ((lane >> 4) << 3)));
#pragma unroll
            for (int ip = 0; ip < 2; ip++)
                ldm_x4(bfr[ip], smem_u32(Bs + (wn * 32 + ip * 16 + ((lane >> 4) << 3) +
                                               (lane & 7)) * SROW + k0 + (lane & 8)));
#pragma unroll
            for (int im = 0; im < 2; im++)
#pragma unroll
                for (int in = 0; in < 4; in++) {
                    int ip = in >> 1, sub = in & 1;
                    mma16816(acc[im][in], af[im], bfr[ip][sub * 2], bfr[ip][sub * 2 + 1]);
                }
        }
    }
#undef LOAD_STAGE

    int g = lane >> 2, tg = lane & 3;
#pragma unroll
    for (int im = 0; im < 2; im++) {
#pragma unroll
        for (int rr = 0; rr < 2; rr++) {
            int m = m0 + wm * 32 + im * 16 + g + rr * 8;
            if (m < M_valid) {
                float* dst = Cb + (size_t)m * HW + n0 + wn * 32 + tg * 2;
#pragma unroll
                for (int in = 0; in < 4; in++) {
                    float2 v = make_float2(acc[im][in][rr * 2], acc[im][in][rr * 2 + 1]);
                    *(float2*)(dst + in * 8) = v;
                }
            }
        }
    }
}

// ---------------- K5: fused dw(q,k) -> bf16 smem -> HMMA dots + fp32 norms ----------------
// 8 output rows per block (1024 px). smem: QK[64][1032] bf16.
#define QKROW 1032
__global__ __launch_bounds__(256)
void k_fused_qk(const float* __restrict__ w_qkvdw) {
    extern __shared__ __nv_bfloat16 QK[];
    int rb = blockIdx.x, bh = blockIdx.y;
    int b = bh >> 3, h = bh & 7;
    int y0 = rb * 8;
    int tid = threadIdx.x, lane = tid & 31, w = tid >> 5;
    int xx = tid & 127, half = tid >> 7;

    // zero pad rows 24-31, 56-63
    for (int i = tid; i < 16 * QKROW; i += 256) {
        int r = i / QKROW, p = i - r * QKROW;
        int row = (r < 8) ? (24 + r) : (48 + r);
        QK[row * QKROW + p] = __float2bfloat16(0.f);
    }

    // conv: thread owns column xx, 8 output rows, channels half, half+2, ...
    for (int j = 0; j < 48; j += 2) {
        int cl = j + half;
        int ch = (cl < 24) ? (h * 24 + cl) : (192 + h * 24 + (cl - 24));
        const float* in = g_qkv + (((size_t)b * C3 + ch) << 14);
        const float* wp = w_qkvdw + ch * 9;
        float wv[9];
#pragma unroll
        for (int i = 0; i < 9; i++) wv[i] = wp[i];
        float o[8];
#pragma unroll
        for (int q = 0; q < 8; q++) o[q] = 0.f;
#pragma unroll
        for (int dy = -1; dy <= 8; dy++) {
            int iy = y0 + dy;
            if (iy < 0 || iy > 127) continue;
            const float* rowp = in + iy * 128;
            float m = rowp[xx];
            float l = (xx > 0) ? rowp[xx - 1] : 0.f;
            float r = (xx < 127) ? rowp[xx + 1] : 0.f;
#pragma unroll
            for (int q = 0; q < 8; q++) {
                int tap = dy - q + 1;
                if (tap >= 0 && tap < 3)
                    o[q] += wv[tap * 3] * l + wv[tap * 3 + 1] * m + wv[tap * 3 + 2] * r;
            }
        }
        int row_s = (cl < 24) ? cl : cl + 8;
        __nv_bfloat16* dst = QK + row_s * QKROW + xx;
#pragma unroll
        for (int q = 0; q < 8; q++) dst[q * 128] = __float2bfloat16(o[q]);
    }
    __syncthreads();

    // fp32 norm partials from bf16 values
    {
        float* np = g_nrm_part + ((size_t)bh * RBQK + rb) * 48;
        for (int chl = w; chl < 48; chl += 8) {
            int row = (chl < 24) ? chl : chl + 8;
            float s = 0.f;
#pragma unroll
            for (int i = 0; i < 32; i++) {
                float v = __bfloat162float(QK[row * QKROW + lane + i * 32]);
                s += v * v;
            }
#pragma unroll
            for (int o2 = 16; o2; o2 >>= 1) s += __shfl_xor_sync(0xffffffffu, s, o2);
            if (lane == 0) np[chl] = s;
        }
    }

    // HMMA dots: warp w handles K range [w*128, w*128+128)
    float acc[2][4][4];
#pragma unroll
    for (int mt = 0; mt < 2; mt++)
#pragma unroll
        for (int n8 = 0; n8 < 4; n8++)
#pragma unroll
            for (int q = 0; q < 4; q++) acc[mt][n8][q] = 0.f;

#pragma unroll
    for (int kt = 0; kt < 8; kt++) {
        int k0 = w * 128 + kt * 16;
        uint32_t am[2][4];
#pragma unroll
        for (int mt = 0; mt < 2; mt++)
            ldm_x4(am[mt], smem_u32(QK + (mt * 16 + (lane & 15)) * QKROW + k0 +
                                    ((lane >> 4) << 3)));
        uint32_t bn[2][4];
#pragma unroll
        for (int nt = 0; nt < 2; nt++)
            ldm_x4(bn[nt], smem_u32(QK + (32 + nt * 16 + ((lane >> 4) << 3) + (lane & 7)) *
                                        QKROW + k0 + (lane & 8)));
#pragma unroll
        for (int mt = 0; mt < 2; mt++)
#pragma unroll
            for (int n8 = 0; n8 < 4; n8++) {
                int nt = n8 >> 1, sub = n8 & 1;
                mma16816(acc[mt][n8], am[mt], bn[nt][sub * 2], bn[nt][sub * 2 + 1]);
            }
    }
    __syncthreads();

    // reduce across warps via smem (overlays QK)
    float* rbuf = (float*)QK;   // 8 * 1024 floats = 32 KB
    int g = lane >> 2, tg = lane & 3;
#pragma unroll
    for (int mt = 0; mt < 2; mt++)
#pragma unroll
        for (int n8 = 0; n8 < 4; n8++) {
            float* base = rbuf + w * 1024 + (mt * 16 + g) * 32 + n8 * 8 + tg * 2;
            base[0] = acc[mt][n8][0];
            base[1] = acc[mt][n8][1];
            base[8 * 32] = acc[mt][n8][2];
            base[8 * 32 + 1] = acc[mt][n8][3];
        }
    __syncthreads();
    float* ap = g_attn_part + ((size_t)bh * RBQK + rb) * 576;
    for (int i = tid; i < 576; i += 256) {
        int c = i / 24, d = i - c * 24;
        float s = 0.f;
#pragma unroll
        for (int w8 = 0; w8 < 8; w8++) s += rbuf[w8 * 1024 + c * 32 + d];
        ap[i] = s;
    }
}

// ---------------- K6: depthwise(v) + split + transpose -> g_V[b][n][384] ----------------
__global__ void k_dwv(const float* __restrict__ w_qkvdw) {
    extern __shared__ unsigned int sh[];   // [256][65]
    int rp = blockIdx.x, cg = blockIdx.y, b = blockIdx.z;
    int t = threadIdx.x;
    int y0 = rp * 2;
    int y = y0 + (t >> 7), xx = t & 127;
    for (int j = 0; j < 64; j++) {
        int ch = 384 + cg * 64 + j;
        const float* in = g_qkv + (((size_t)b * C3 + ch) << 14);
        const float* wp = w_qkvdw + ch * 9;
        float wv[9];
#pragma unroll
        for (int i = 0; i < 9; i++) wv[i] = wp[i];
        float a = 0.f;
#pragma unroll
        for (int dy = 0; dy < 3; dy++) {
            int yy = y + dy - 1;
            if (yy < 0 || yy > 127) continue;
            const float* row = in + yy * 128;
#pragma unroll
            for (int dx = 0; dx < 3; dx++) {
                int xc = xx + dx - 1;
                if (xc < 0 || xc > 127) continue;
                a += wv[dy * 3 + dx] * row[xc];
            }
        }
        sh[t * 65 + j] = bfsplit_pack(a);
    }
    __syncthreads();
    __nv_bfloat16* Vb = g_V + (size_t)b * HW * KB_PHYS;
    int lane = t & 31, w = t >> 5;
    int n0 = y0 * 128;
    for (int r = w; r < 256; r += 8) {
        unsigned int e0 = sh[r * 65 + lane * 2];
        unsigned int e1 = sh[r * 65 + lane * 2 + 1];
        unsigned int hi2 = (e0 & 0xFFFFu) | (e1 << 16);
        unsigned int lo2 = (e0 >> 16) | (e1 & 0xFFFF0000u);
        size_t rowb = (size_t)(n0 + r) * KB_PHYS + cg * 64 + lane * 2;
        *(unsigned int*)(Vb + rowb) = hi2;
        *(unsigned int*)(Vb + rowb + 192) = lo2;
    }
}

// ---------------- K7: finalize attention ----------------
__global__ void k_attn_fin(const float* __restrict__ temperature,
                           const float* __restrict__ rescale) {
    int bh = blockIdx.x;
    int b = bh >> 3, h = bh & 7;
    int c = threadIdx.x >> 5, lane = threadIdx.x & 31;
    float val;
    if (lane < 24) {
        float raw = 0.f, nq2 = 0.f, nk2 = 0.f;
        for (int s = 0; s < RBQK; s++) {
            const float* ap = g_attn_part + ((size_t)bh * RBQK + s) * 576;
            const float* np = g_nrm_part + ((size_t)bh * RBQK + s) * 48;
            raw += ap[c * 24 + lane];
            nq2 += np[c];
            nk2 += np[24 + lane];
        }
        float nq = sqrtf(nq2), nk = sqrtf(nk2);
        val = raw / (fmaxf(nq, 1e-12f) * fmaxf(nk, 1e-12f)) * temperature[h];
        if (c == lane) val += rescale[h] * g_var[b * CDIM + h * 24 + c];
    } else {
        val = -INFINITY;
    }
    float mx = val;
#pragma unroll
    for (int o = 16; o; o >>= 1) mx = fmaxf(mx, __shfl_xor_sync(0xffffffffu, mx, o));
    float ex = (lane < 24) ? expf(val - mx) : 0.f;
    float sm = ex;
#pragma unroll
    for (int o = 16; o; o >>= 1) sm += __shfl_xor_sync(0xffffffffu, sm, o);
    if (lane < 24) g_attn[(size_t)bh * 576 + c * 24 + lane] = ex / sm;
}

// ---------------- K8: W2 = w_proj @ blockdiag(attn) -> g_A2 [Wh | Wh | Wl] ----------------
__global__ void k_w2(const float* __restrict__ w_proj) {
    int bh = blockIdx.x;
    int b = bh >> 3, h = bh & 7;
    int co = threadIdx.x;
    __shared__ float at[24][24];
    for (int i = co; i < 576; i += 192) at[i / 24][i % 24] = g_attn[(size_t)bh * 576 + i];
    __syncthreads();
    float wpv[24];
#pragma unroll
    for (int cc = 0; cc < 24; cc++) wpv[cc] = w_proj[co * CDIM + h * 24 + cc];
    __nv_bfloat16* A2 = g_A2 + (size_t)b * 256 * KTOT + (size_t)co * KTOT;
#pragma unroll
    for (int d = 0; d < 24; d++) {
        float a = 0.f;
#pragma unroll
        for (int cc = 0; cc < 24; cc++) a += wpv[cc] * at[cc][d];
        unsigned int pk = bfsplit_pack(a);
        A2[h * 24 + d] = __ushort_as_bfloat16((unsigned short)(pk & 0xFFFF));
        A2[192 + h * 24 + d] = __ushort_as_bfloat16((unsigned short)(pk & 0xFFFF));
        A2[384 + h * 24 + d] = __ushort_as_bfloat16((unsigned short)(pk >> 16));
    }
}

// ---------------- launch ----------------
extern "C" void kernel_launch(void* const* d_in, const int* in_sizes, int n_in,
                              void* d_out, int out_size) {
    const float* x           = (const float*)d_in[0];
    const float* w_dw        = (const float*)d_in[1];
    const float* w_qkv       = (const float*)d_in[2];
    const float* w_qkvdw     = (const float*)d_in[3];
    const float* w_proj      = (const float*)d_in[4];
    const float* temperature = (const float*)d_in[5];
    const float* rescale     = (const float*)d_in[6];
    float* out = (float*)d_out;

    float* p_qkv;
    __nv_bfloat16 *p_A1, *p_B1, *p_A2, *p_V;
    cudaGetSymbolAddress((void**)&p_qkv, g_qkv);
    cudaGetSymbolAddress((void**)&p_A1, g_A1);
    cudaGetSymbolAddress((void**)&p_B1, g_B1);
    cudaGetSymbolAddress((void**)&p_A2, g_A2);
    cudaGetSymbolAddress((void**)&p_V, g_V);

    const int GEMM_SMEM = STAGES * (BM + BN) * SROW * 2;   // 55296
    const int QK_SMEM = 64 * QKROW * 2;                    // 132096
    static bool attr_set = false;
    if (!attr_set) {
        cudaFuncSetAttribute(k_gemm_mma, cudaFuncAttributeMaxDynamicSharedMemorySize, GEMM_SMEM);
        cudaFuncSetAttribute(k_fused_qk, cudaFuncAttributeMaxDynamicSharedMemorySize, QK_SMEM);
        cudaFuncSetAttribute(k_splitB, cudaFuncAttributeMaxDynamicSharedMemorySize, 66560);
        cudaFuncSetAttribute(k_dwv, cudaFuncAttributeMaxDynamicSharedMemorySize, 66560);
        attr_set = true;
    }

    k_var<<<BATCH * CDIM, 256>>>(x, w_dw);
    k_splitB<<<dim3(64, 3, BATCH), 256, 66560>>>(x);
    k_prepA1<<<C3, CDIM>>>(w_qkv);
    k_gemm_mma<<<dim3(HW / BN, 5, BATCH), 256, GEMM_SMEM>>>(
        p_A1, p_B1, p_qkv, C3, 0LL, (long long)HW * KB_PHYS, (long long)C3 * HW);
    k_fused_qk<<<dim3(RBQK, BATCH * HEADS), 256, QK_SMEM>>>(w_qkvdw);
    k_dwv<<<dim3(64, 3, BATCH), 256, 66560>>>(w_qkvdw);
    k_attn_fin<<<BATCH * HEADS, CH * 32>>>(temperature, rescale);
    k_w2<<<BATCH * HEADS, CDIM>>>(w_proj);
    k_gemm_mma<<<dim3(HW / BN, 2, BATCH), 256, GEMM_SMEM>>>(
        p_A2, p_V, out, CDIM, 256LL * KTOT, (long long)HW * KB_PHYS, (long long)CDIM * HW);
}